// round 12
// baseline (speedup 1.0000x reference)
#include <cuda_runtime.h>
#include <math.h>
#include <stdint.h>
#include <stddef.h>

// ---------------- problem constants ----------------
#define NN    131072
#define DD    768
#define NKPT_ 17
#define MC    10
#define KM    170          // NKPT*M
#define KMP   176          // padded GEMM column count
#define EPS_F 0.05f

// ---------------- device scratch (no allocations allowed) ----------------
__device__ float    g_protoN[KMP * DD];   // normalized prototypes, rows 170..175 zero
__device__ float    g_invn[NN];           // 1 / max(||feats_n||, 1e-12)
__device__ float    g_L[MC * NN];         // sinkhorn state, column-major [m][n]
__device__ float    g_ce[NN];             // conf_eff
__device__ float    g_col[3][KM];         // column sums per iteration
__device__ float    g_cnt[NKPT_];         // member counts B_k (float)
__device__ float    g_nsum[KM];           // n[k,m]
__device__ float    g_f[KM * DD];         // f accumulator
__device__ unsigned g_keys[NKPT_][2];     // per-class threefry keys
__device__ int      g_list[NN];
__device__ int      g_hj[NN];
__device__ float    g_w2[NN];
__device__ int      g_nconf;

// ---------------- threefry2x32 (matches JAX) ----------------
__device__ __forceinline__ void threefry2x32(unsigned k0, unsigned k1,
                                             unsigned x0, unsigned x1,
                                             unsigned& o0, unsigned& o1) {
    unsigned ks2 = k0 ^ k1 ^ 0x1BD11BDAu;
    x0 += k0; x1 += k1;
#define TFR(r) { x0 += x1; x1 = (x1 << (r)) | (x1 >> (32 - (r))); x1 ^= x0; }
    TFR(13) TFR(15) TFR(26) TFR(6)  x0 += k1;  x1 += ks2 + 1u;
    TFR(17) TFR(29) TFR(16) TFR(24) x0 += ks2; x1 += k0 + 2u;
    TFR(13) TFR(15) TFR(26) TFR(6)  x0 += k0;  x1 += k1 + 3u;
    TFR(17) TFR(29) TFR(16) TFR(24) x0 += k1;  x1 += ks2 + 4u;
    TFR(13) TFR(15) TFR(26) TFR(6)  x0 += ks2; x1 += k0 + 5u;
#undef TFR
    o0 = x0; o1 = x1;
}

__device__ __forceinline__ float blockReduceSum256(float v, float* red) {
    int tid = threadIdx.x;
    red[tid] = v;
    __syncthreads();
#pragma unroll
    for (int s = 128; s > 0; s >>= 1) {
        if (tid < s) red[tid] += red[tid + s];
        __syncthreads();
    }
    float r = red[0];
    __syncthreads();
    return r;
}

// ---------------- kernels ----------------

__global__ void k_init() {
    int i = blockIdx.x * 256 + threadIdx.x;
    if (i < KM * DD) g_f[i] = 0.f;
    if (i < 3 * KM)  ((float*)g_col)[i] = 0.f;
    if (i < KM)      g_nsum[i] = 0.f;
    if (i < NKPT_)   g_cnt[i] = 0.f;
    if (i == 0)      g_nconf = 0;
}

__global__ void k_keys() {
    int t = threadIdx.x;
    if (t < NKPT_) {
        unsigned a, b;
        threefry2x32(0u, 42u, 0u, (unsigned)t, a, b);
        g_keys[t][0] = a; g_keys[t][1] = b;
    }
}

// normalize prototypes, pad rows 170..175 with zeros
__global__ __launch_bounds__(256) void k_pnorm(const float* __restrict__ P) {
    __shared__ float red[256];
    int j = blockIdx.x;
    int tid = threadIdx.x;
    if (j >= KM) {
        for (int d = tid; d < DD; d += 256) g_protoN[(size_t)j * DD + d] = 0.f;
        return;
    }
    const float* p = P + (size_t)j * DD;
    float s = 0.f;
    for (int d = tid; d < DD; d += 256) { float x = p[d]; s += x * x; }
    float tot = blockReduceSum256(s, red);
    float inv = 1.0f / fmaxf(sqrtf(tot), 1e-12f);
    for (int d = tid; d < DD; d += 256) g_protoN[(size_t)j * DD + d] = p[d] * inv;
}

// per-row inverse norms of feats (warp per row)
__global__ __launch_bounds__(256) void k_invn(const float* __restrict__ A) {
    int t = blockIdx.x * 256 + threadIdx.x;
    int w = t >> 5, lane = t & 31;
    int nw = (gridDim.x * 256) >> 5;
    for (int row = w; row < NN; row += nw) {
        const float4* p = (const float4*)(A + (size_t)row * DD);
        float s = 0.f;
#pragma unroll 6
        for (int c = lane; c < DD / 4; c += 32) {
            float4 v = p[c];
            s += v.x * v.x + v.y * v.y + v.z * v.z + v.w * v.w;
        }
#pragma unroll
        for (int o = 16; o > 0; o >>= 1) s += __shfl_xor_sync(0xffffffffu, s, o);
        if (lane == 0) g_invn[row] = 1.0f / fmaxf(sqrtf(s), 1e-12f);
    }
}

// sim GEMM: outSim[n, j] = |dot(feats[n], protoN[j])| * invn[n], j < 170
// block tile 128x176, 256 threads (16x16), per-thread 8x11
__global__ __launch_bounds__(256) void k_gemm(const float* __restrict__ A,
                                              float* __restrict__ outSim) {
    __shared__ float As[16][128];
    __shared__ float Bs[16][KMP];
    const int tid = threadIdx.x;
    const int tx = tid & 15;
    const int ty = tid >> 4;
    const int bm = blockIdx.x * 128;
    float acc[8][11];
#pragma unroll
    for (int i = 0; i < 8; i++)
#pragma unroll
        for (int j = 0; j < 11; j++) acc[i][j] = 0.f;

    for (int k0 = 0; k0 < DD; k0 += 16) {
#pragma unroll
        for (int t = 0; t < 2; t++) {
            int f4 = tid * 2 + t;              // 0..511
            int row = f4 >> 2;
            int c4 = (f4 & 3) << 2;
            float4 v = *(const float4*)(A + (size_t)(bm + row) * DD + k0 + c4);
            As[c4 + 0][row] = v.x; As[c4 + 1][row] = v.y;
            As[c4 + 2][row] = v.z; As[c4 + 3][row] = v.w;
        }
        for (int f4 = tid; f4 < (KMP * 16) / 4; f4 += 256) {
            int row = f4 >> 2;
            int c4 = (f4 & 3) << 2;
            float4 v = *(const float4*)(&g_protoN[(size_t)row * DD + k0 + c4]);
            Bs[c4 + 0][row] = v.x; Bs[c4 + 1][row] = v.y;
            Bs[c4 + 2][row] = v.z; Bs[c4 + 3][row] = v.w;
        }
        __syncthreads();
#pragma unroll
        for (int kk = 0; kk < 16; kk++) {
            float a[8], b[11];
            const float4* ap = (const float4*)&As[kk][ty << 3];
            float4 a0 = ap[0], a1 = ap[1];
            a[0] = a0.x; a[1] = a0.y; a[2] = a0.z; a[3] = a0.w;
            a[4] = a1.x; a[5] = a1.y; a[6] = a1.z; a[7] = a1.w;
#pragma unroll
            for (int j = 0; j < 11; j++) b[j] = Bs[kk][tx * 11 + j];
#pragma unroll
            for (int i = 0; i < 8; i++)
#pragma unroll
                for (int j = 0; j < 11; j++) acc[i][j] = fmaf(a[i], b[j], acc[i][j]);
        }
        __syncthreads();
    }
#pragma unroll
    for (int i = 0; i < 8; i++) {
        int row = bm + (ty << 3) + i;
        float sc = g_invn[row];
#pragma unroll
        for (int j = 0; j < 11; j++) {
            int col = tx * 11 + j;
            if (col < KM) outSim[(size_t)row * KM + col] = fabsf(acc[i][j] * sc);
        }
    }
}

// epilogue: per-row argmax/clip, conf_eff, L0 = exp(sim/eps), colsum0, counts
__global__ __launch_bounds__(256) void k_epi(const float* __restrict__ sim,
                                             const int* __restrict__ gt,
                                             const float* __restrict__ conf,
                                             float* __restrict__ outKpt) {
    __shared__ float ssim[8][KMP];
    __shared__ float scol[KM];
    __shared__ float scnt[NKPT_];
    int tid = threadIdx.x;
    if (tid < KM) scol[tid] = 0.f;
    if (tid < NKPT_) scnt[tid] = 0.f;
    __syncthreads();
    int w = tid >> 5, lane = tid & 31;
    int warpsTotal = gridDim.x * 8;
    for (int n = blockIdx.x * 8 + w; n < NN; n += warpsTotal) {
        const float* srow = sim + (size_t)n * KM;
        for (int j = lane; j < KM; j += 32) ssim[w][j] = srow[j];
        __syncwarp();
        float mx = -1.f; int bi = 17;
        if (lane < NKPT_) {
            mx = ssim[w][lane * 10];
#pragma unroll
            for (int i = 1; i < 10; i++) mx = fmaxf(mx, ssim[w][lane * 10 + i]);
            bi = lane;
        }
        float v = mx; int ii = bi;
#pragma unroll
        for (int o = 16; o > 0; o >>= 1) {
            float v2 = __shfl_xor_sync(0xffffffffu, v, o);
            int i2 = __shfl_xor_sync(0xffffffffu, ii, o);
            if (v2 > v || (v2 == v && i2 < ii)) { v = v2; ii = i2; }
        }
        int pred = ii;
        int g = gt[n];
        if (lane < NKPT_) {
            float c = fminf(fmaxf(mx, 1e-4f), 0.9999f);
            outKpt[(size_t)n * NKPT_ + lane] = c;
        }
        if (lane == 0) {
            float ce = (g == pred) ? conf[n] : 0.f;
            g_ce[n] = ce;
            atomicAdd(&scnt[g], 1.0f);
        }
        if (lane < MC) {
            float e = expf(ssim[w][g * 10 + lane] / EPS_F);
            g_L[lane * NN + n] = e;
            atomicAdd(&scol[g * 10 + lane], e);
        }
        __syncwarp();
    }
    __syncthreads();
    if (tid < KM) atomicAdd(&g_col[0][tid], scol[tid]);
    if (tid < NKPT_) atomicAdd(&g_cnt[tid], scnt[tid]);
}

// one sinkhorn iteration (col step + row step), accumulate next colsum
__global__ __launch_bounds__(256) void k_sstep(const int* __restrict__ gt, int it) {
    __shared__ float scol[KM];
    int tid = threadIdx.x;
    if (tid < KM) scol[tid] = 0.f;
    __syncthreads();
    int n = blockIdx.x * 256 + tid;
    if (n < NN) {
        int g = gt[n];
        float B = g_cnt[g];
        float Lv[MC];
        float rs = 0.f;
#pragma unroll
        for (int m = 0; m < MC; m++) {
            float l = g_L[m * NN + n];
            float t = l / (g_col[it][g * 10 + m] * 10.0f);
            Lv[m] = t; rs += t;
        }
        float den = rs * B;
#pragma unroll
        for (int m = 0; m < MC; m++) {
            float t = (rs > 0.f) ? Lv[m] / den : 0.f;
            g_L[m * NN + n] = t;
            atomicAdd(&scol[g * 10 + m], t);
        }
    }
    __syncthreads();
    if (tid < KM) atomicAdd(&g_col[it + 1][tid], scol[tid]);
}

// final iteration: idx argmax, gumbel hard assignment, compact conf list
__global__ __launch_bounds__(256) void k_s3(const int* __restrict__ gt,
                                            float* __restrict__ outTgt) {
    int n = blockIdx.x * 256 + threadIdx.x;
    if (n >= NN) return;
    int g = gt[n];
    float B = g_cnt[g];
    float t[MC];
    float rs = 0.f;
#pragma unroll
    for (int m = 0; m < MC; m++) {
        t[m] = g_L[m * NN + n] / (g_col[2][g * 10 + m] * 10.0f);
        rs += t[m];
    }
    int idx = 0; float bv = t[0];
#pragma unroll
    for (int m = 1; m < MC; m++) if (t[m] > bv) { bv = t[m]; idx = m; }
    float den = rs * B;
    unsigned kk0 = g_keys[g][0], kk1 = g_keys[g][1];
    int h = 0; float bh = -1e30f;
#pragma unroll
    for (int m = 0; m < MC; m++) {
        float a = (rs > 0.f) ? t[m] / den : 0.f;
        float Lf = a * B;
        unsigned j = (unsigned)(n * 10 + m);
        unsigned b0, b1;
        threefry2x32(kk0, kk1, 0u, j, b0, b1);
        unsigned bits = b0 ^ b1;
        float u = __uint_as_float((bits >> 9) | 0x3f800000u) - 1.0f;
        u = fmaxf(u, 1.17549435e-38f);
        float gb = -logf(-logf(u));
        float cand = Lf + gb;
        if (cand > bh) { bh = cand; h = m; }
    }
    outTgt[n] = (float)(idx + 10 * g);
    float ce = g_ce[n];
    if (ce > 0.f) {
        int p = atomicAdd(&g_nconf, 1);
        g_list[p] = n;
        g_hj[n] = h;
        g_w2[n] = ce * ce * g_invn[n];
        atomicAdd(&g_nsum[g * 10 + h], ce);
    }
}

// accumulate f[k,m,:] += ce^2 * featsN[n,:]  (warp per listed row)
__global__ __launch_bounds__(256) void k_faccum(const float* __restrict__ A,
                                                const int* __restrict__ gt) {
    int t = blockIdx.x * 256 + threadIdx.x;
    int w = t >> 5, lane = t & 31;
    int nw = (gridDim.x * 256) >> 5;
    int cnt = g_nconf;
    for (int i = w; i < cnt; i += nw) {
        int n = g_list[i];
        int g = gt[n];
        int h = g_hj[n];
        float w2 = g_w2[n];
        float* frow = &g_f[(size_t)(g * 10 + h) * DD];
        const float4* a = (const float4*)(A + (size_t)n * DD);
#pragma unroll 6
        for (int c = lane; c < DD / 4; c += 32) {
            float4 v = a[c];
            atomicAdd(&frow[4 * c + 0], w2 * v.x);
            atomicAdd(&frow[4 * c + 1], w2 * v.y);
            atomicAdd(&frow[4 * c + 2], w2 * v.z);
            atomicAdd(&frow[4 * c + 3], w2 * v.w);
        }
    }
}

// prototype EMA update + renormalization (block per (k,m))
__global__ __launch_bounds__(256) void k_newproto(float* __restrict__ outNP) {
    __shared__ float red[256];
    __shared__ float buf[DD];
    __shared__ int sup;
    int km = blockIdx.x;
    int k = km / MC;
    int tid = threadIdx.x;
    if (tid == 0) {
        float s = 0.f;
#pragma unroll
        for (int i = 0; i < MC; i++) s += g_nsum[k * MC + i];
        sup = (s > 0.f && g_nsum[km] != 0.f) ? 1 : 0;
    }
    float fs = 0.f;
    for (int d = tid; d < DD; d += 256) { float v = g_f[(size_t)km * DD + d]; fs += v * v; }
    float ftot = blockReduceSum256(fs, red);
    float finv = 1.0f / fmaxf(sqrtf(ftot), 1e-12f);
    int upd = sup;
    float vs = 0.f;
    for (int d = tid; d < DD; d += 256) {
        float pN = g_protoN[(size_t)km * DD + d];
        float fn = g_f[(size_t)km * DD + d] * finv;
        float val = upd ? (0.999f * pN + 0.001f * fn) : pN;
        buf[d] = val;
        vs += val * val;
    }
    float vtot = blockReduceSum256(vs, red);
    float vinv = 1.0f / fmaxf(sqrtf(vtot), 1e-12f);
    for (int d = tid; d < DD; d += 256)
        outNP[(size_t)km * DD + d] = buf[d] * vinv;
}

// ---------------- launch ----------------
extern "C" void kernel_launch(void* const* d_in, const int* in_sizes, int n_in,
                              void* d_out, int out_size) {
    const float* feats = (const float*)d_in[0];
    const int*   gt    = (const int*)d_in[1];
    const float* conf  = (const float*)d_in[2];
    const float* proto = (const float*)d_in[3];

    float* out  = (float*)d_out;
    float* oLog = out;                                 // N*170
    float* oTgt = oLog + (size_t)NN * KM;              // N
    float* oKpt = oTgt + NN;                           // N*17
    float* oNP  = oKpt + (size_t)NN * NKPT_;           // 170*768

    k_init<<<(KM * DD + 255) / 256, 256>>>();
    k_keys<<<1, 32>>>();
    k_pnorm<<<KMP, 256>>>(proto);
    k_invn<<<512, 256>>>(feats);
    k_gemm<<<NN / 128, 256>>>(feats, oLog);
    k_epi<<<512, 256>>>(oLog, gt, conf, oKpt);
    k_sstep<<<NN / 256, 256>>>(gt, 0);
    k_sstep<<<NN / 256, 256>>>(gt, 1);
    k_s3<<<NN / 256, 256>>>(gt, oTgt);
    k_faccum<<<512, 256>>>(feats, gt);
    k_newproto<<<KM, 256>>>(oNP);
}

// round 14
// speedup vs baseline: 2.9174x; 2.9174x over previous
#include <cuda_runtime.h>
#include <cuda_bf16.h>
#include <math.h>
#include <stdint.h>
#include <stddef.h>

// ---------------- problem constants ----------------
#define NN    131072
#define DD    768
#define NKPT_ 17
#define MC    10
#define KM    170          // NKPT*M
#define KMP   176          // padded column count
#define EPS_F 0.05f
#define KC    64           // K chunk
#define NCHUNK 12          // DD/KC

// GEMM smem: rows padded to 72 halves (144 B) -> conflict-free 32b frag loads
#define PADK   72
#define STG_A  (128 * PADK * 2)          // 18432 B per A buffer
#define STG_B  (176 * PADK * 2)          // 25344 B per B buffer
#define OFF_AHI 0
#define OFF_ALO STG_A
#define OFF_BHI (2 * STG_A)
#define OFF_BLO (2 * STG_A + STG_B)
#define STAGE   (2 * STG_A + 2 * STG_B)  // 87552 B
#define SMEM_GEMM (2 * STAGE + 512)

// ---------------- device scratch (no allocations allowed) ----------------
__device__ __nv_bfloat16 g_Bhi[KMP * DD];  // normalized protos hi (rows 170..175 zero)
__device__ __nv_bfloat16 g_Blo[KMP * DD];  // normalized protos lo
__device__ float    g_protoN[KM * DD];     // normalized prototypes fp32 (for EMA)
__device__ float    g_invn[NN];            // 1 / max(||feats_n||, 1e-12)
__device__ float    g_L[MC * NN];          // sinkhorn state, column-major [m][n]
__device__ float    g_ce[NN];              // conf_eff
__device__ float    g_col[3][KM];          // column sums per iteration
__device__ float    g_cnt[NKPT_];          // member counts B_k
__device__ float    g_nsum[KM];            // n[k,m]
__device__ float    g_f[KM * DD];          // f accumulator
__device__ unsigned g_keys[NKPT_][2];      // per-class threefry keys
__device__ int      g_list[NN];
__device__ int      g_hj[NN];
__device__ float    g_w2[NN];
__device__ int      g_nconf;

// ---------------- helpers ----------------
__device__ __forceinline__ uint32_t smem_u32(const void* p) {
    uint32_t a;
    asm("{ .reg .u64 t; cvta.to.shared.u64 t, %1; cvt.u32.u64 %0, t; }" : "=r"(a) : "l"(p));
    return a;
}

__device__ __forceinline__ unsigned lds32(uint32_t a) {
    unsigned v;
    asm volatile("ld.shared.b32 %0, [%1];" : "=r"(v) : "r"(a));
    return v;
}

__device__ __forceinline__ void cpasync8(uint32_t dst, const void* src) {
    asm volatile("cp.async.ca.shared.global [%0], [%1], 8;" :: "r"(dst), "l"(src) : "memory");
}

__device__ __forceinline__ void mma16816(float* d, const unsigned* a, const unsigned* b) {
    asm volatile(
        "mma.sync.aligned.m16n8k16.row.col.f32.bf16.bf16.f32 "
        "{%0,%1,%2,%3}, {%4,%5,%6,%7}, {%8,%9}, {%0,%1,%2,%3};"
        : "+f"(d[0]), "+f"(d[1]), "+f"(d[2]), "+f"(d[3])
        : "r"(a[0]), "r"(a[1]), "r"(a[2]), "r"(a[3]), "r"(b[0]), "r"(b[1]));
}

__device__ __forceinline__ void split2(float x, float y, unsigned& h, unsigned& l) {
    __nv_bfloat16 hx = __float2bfloat16(x), hy = __float2bfloat16(y);
    float rx = x - __bfloat162float(hx), ry = y - __bfloat162float(hy);
    __nv_bfloat16 lx = __float2bfloat16(rx), ly = __float2bfloat16(ry);
    h = (unsigned)__bfloat16_as_ushort(hx) | ((unsigned)__bfloat16_as_ushort(hy) << 16);
    l = (unsigned)__bfloat16_as_ushort(lx) | ((unsigned)__bfloat16_as_ushort(ly) << 16);
}

// ---------------- threefry2x32 (matches JAX) ----------------
__device__ __forceinline__ void threefry2x32(unsigned k0, unsigned k1,
                                             unsigned x0, unsigned x1,
                                             unsigned& o0, unsigned& o1) {
    unsigned ks2 = k0 ^ k1 ^ 0x1BD11BDAu;
    x0 += k0; x1 += k1;
#define TFR(r) { x0 += x1; x1 = (x1 << (r)) | (x1 >> (32 - (r))); x1 ^= x0; }
    TFR(13) TFR(15) TFR(26) TFR(6)  x0 += k1;  x1 += ks2 + 1u;
    TFR(17) TFR(29) TFR(16) TFR(24) x0 += ks2; x1 += k0 + 2u;
    TFR(13) TFR(15) TFR(26) TFR(6)  x0 += k0;  x1 += k1 + 3u;
    TFR(17) TFR(29) TFR(16) TFR(24) x0 += k1;  x1 += ks2 + 4u;
    TFR(13) TFR(15) TFR(26) TFR(6)  x0 += ks2; x1 += k0 + 5u;
#undef TFR
    o0 = x0; o1 = x1;
}

__device__ __forceinline__ float blockReduceSum256(float v, float* red) {
    int tid = threadIdx.x;
    red[tid] = v;
    __syncthreads();
#pragma unroll
    for (int s = 128; s > 0; s >>= 1) {
        if (tid < s) red[tid] += red[tid + s];
        __syncthreads();
    }
    float r = red[0];
    __syncthreads();
    return r;
}

// ---------------- kernels ----------------

__global__ void k_init() {
    int i = blockIdx.x * 256 + threadIdx.x;
    if (i < KM * DD) g_f[i] = 0.f;
    if (i < 3 * KM)  ((float*)g_col)[i] = 0.f;
    if (i < KM)      g_nsum[i] = 0.f;
    if (i < NKPT_)   g_cnt[i] = 0.f;
    if (i == 0)      g_nconf = 0;
}

__global__ void k_keys() {
    int t = threadIdx.x;
    if (t < NKPT_) {
        unsigned a, b;
        threefry2x32(0u, 42u, 0u, (unsigned)t, a, b);
        g_keys[t][0] = a; g_keys[t][1] = b;
    }
}

// normalize prototypes -> fp32 + bf16 hi/lo
__global__ __launch_bounds__(256) void k_pnorm(const float* __restrict__ P) {
    __shared__ float red[256];
    int j = blockIdx.x;   // 0..169
    int tid = threadIdx.x;
    const float* p = P + (size_t)j * DD;
    float s = 0.f;
    for (int d = tid; d < DD; d += 256) { float x = p[d]; s += x * x; }
    float tot = blockReduceSum256(s, red);
    float inv = 1.0f / fmaxf(sqrtf(tot), 1e-12f);
    for (int d = tid; d < DD; d += 256) {
        float v = p[d] * inv;
        g_protoN[(size_t)j * DD + d] = v;
        __nv_bfloat16 h = __float2bfloat16(v);
        __nv_bfloat16 l = __float2bfloat16(v - __bfloat162float(h));
        g_Bhi[(size_t)j * DD + d] = h;
        g_Blo[(size_t)j * DD + d] = l;
    }
}

// ---------------- tensor-core GEMM (mma.sync, bf16x3 split) ----------------
// Fused: per-row inv-norm of feats + fp32->bf16 hi/lo staging + GEMM + |.|*invn.
// CTA tile 128 x 176, 8 warps (4M x 2N), warp tile 32 x 88 (2 x 11 mma tiles).
__global__ void __launch_bounds__(256, 1) k_gemm_mma(const float* __restrict__ A,
                                                     float* __restrict__ outSim) {
    extern __shared__ char smem[];
    float* sInv = (float*)(smem + 2 * STAGE);
    const uint32_t sbase = smem_u32(smem);
    const int tid = threadIdx.x;
    const int wid = tid >> 5, lane = tid & 31;
    const int g = lane >> 2, tig = lane & 3;
    const int bm = blockIdx.x * 128;
    const int warpM = (wid >> 1) * 32;
    const int warpN = (wid & 1) * 88;

    float rsq[8];
    float acc[2][11][4];
    float4 pref[8];
#pragma unroll
    for (int j = 0; j < 8; j++) rsq[j] = 0.f;
#pragma unroll
    for (int mi = 0; mi < 2; mi++)
#pragma unroll
        for (int ni = 0; ni < 11; ni++)
#pragma unroll
            for (int q = 0; q < 4; q++) acc[mi][ni][q] = 0.f;

    // ---- staging lambdas ----
    auto loadB = [&](int c, int st) {
        const int k0 = c * KC;
        uint32_t dhi = sbase + (uint32_t)(st * STAGE + OFF_BHI);
        uint32_t dlo = sbase + (uint32_t)(st * STAGE + OFF_BLO);
#pragma unroll
        for (int i = 0; i < 11; i++) {
            int id = tid + 256 * i;
            int row = id >> 4, col = (id & 15) * 4;
            uint32_t off = (uint32_t)(row * (PADK * 2) + col * 2);
            cpasync8(dhi + off, g_Bhi + (size_t)row * DD + k0 + col);
            cpasync8(dlo + off, g_Blo + (size_t)row * DD + k0 + col);
        }
        asm volatile("cp.async.commit_group;" ::: "memory");
    };
    auto prefA = [&](int c) {
        const int k0 = c * KC;
#pragma unroll
        for (int j = 0; j < 8; j++) {
            int id = tid + 256 * j;
            int row = id >> 4, col = (id & 15) * 4;
            pref[j] = *(const float4*)(A + (size_t)(bm + row) * DD + k0 + col);
        }
    };
    auto stsA = [&](int st) {
        char* base = smem + st * STAGE;
        __nv_bfloat16* ahi = (__nv_bfloat16*)(base + OFF_AHI);
        __nv_bfloat16* alo = (__nv_bfloat16*)(base + OFF_ALO);
#pragma unroll
        for (int j = 0; j < 8; j++) {
            int id = tid + 256 * j;
            int row = id >> 4, col = (id & 15) * 4;
            float4 v = pref[j];
            rsq[j] += v.x * v.x + v.y * v.y + v.z * v.z + v.w * v.w;
            unsigned h01, l01, h23, l23;
            split2(v.x, v.y, h01, l01);
            split2(v.z, v.w, h23, l23);
            *(uint2*)(ahi + row * PADK + col) = make_uint2(h01, h23);
            *(uint2*)(alo + row * PADK + col) = make_uint2(l01, l23);
        }
    };
    auto compute = [&](int st) {
        uint32_t aHi = sbase + (uint32_t)(st * STAGE + OFF_AHI);
        uint32_t aLo = aHi + STG_A;
        uint32_t bHi = sbase + (uint32_t)(st * STAGE + OFF_BHI);
        uint32_t bLo = bHi + STG_B;
#pragma unroll
        for (int ks = 0; ks < 4; ks++) {
            const int kb = (ks * 16 + 2 * tig) * 2;   // byte offset of k within row
            unsigned af[2][4], bf[11][2];
            // --- A hi frags ---
#pragma unroll
            for (int mi = 0; mi < 2; mi++) {
                uint32_t r0 = aHi + (uint32_t)((warpM + mi * 16 + g) * (PADK * 2) + kb);
                af[mi][0] = lds32(r0);
                af[mi][1] = lds32(r0 + 8 * (PADK * 2));
                af[mi][2] = lds32(r0 + 16);
                af[mi][3] = lds32(r0 + 8 * (PADK * 2) + 16);
            }
            // --- B hi frags ---
#pragma unroll
            for (int ni = 0; ni < 11; ni++) {
                uint32_t r0 = bHi + (uint32_t)((warpN + ni * 8 + g) * (PADK * 2) + kb);
                bf[ni][0] = lds32(r0);
                bf[ni][1] = lds32(r0 + 16);
            }
            // pass 0: Ahi * Bhi
#pragma unroll
            for (int mi = 0; mi < 2; mi++)
#pragma unroll
                for (int ni = 0; ni < 11; ni++)
                    mma16816(acc[mi][ni], af[mi], bf[ni]);
            // pass 1: Alo * Bhi (reuse B frags)
#pragma unroll
            for (int mi = 0; mi < 2; mi++) {
                uint32_t r0 = aLo + (uint32_t)((warpM + mi * 16 + g) * (PADK * 2) + kb);
                af[mi][0] = lds32(r0);
                af[mi][1] = lds32(r0 + 8 * (PADK * 2));
                af[mi][2] = lds32(r0 + 16);
                af[mi][3] = lds32(r0 + 8 * (PADK * 2) + 16);
            }
#pragma unroll
            for (int mi = 0; mi < 2; mi++)
#pragma unroll
                for (int ni = 0; ni < 11; ni++)
                    mma16816(acc[mi][ni], af[mi], bf[ni]);
            // pass 2: Ahi * Blo
#pragma unroll
            for (int mi = 0; mi < 2; mi++) {
                uint32_t r0 = aHi + (uint32_t)((warpM + mi * 16 + g) * (PADK * 2) + kb);
                af[mi][0] = lds32(r0);
                af[mi][1] = lds32(r0 + 8 * (PADK * 2));
                af[mi][2] = lds32(r0 + 16);
                af[mi][3] = lds32(r0 + 8 * (PADK * 2) + 16);
            }
#pragma unroll
            for (int ni = 0; ni < 11; ni++) {
                uint32_t r0 = bLo + (uint32_t)((warpN + ni * 8 + g) * (PADK * 2) + kb);
                bf[ni][0] = lds32(r0);
                bf[ni][1] = lds32(r0 + 16);
            }
#pragma unroll
            for (int mi = 0; mi < 2; mi++)
#pragma unroll
                for (int ni = 0; ni < 11; ni++)
                    mma16816(acc[mi][ni], af[mi], bf[ni]);
        }
    };

    // ---- pipeline ----
    loadB(0, 0);
    prefA(0);
    stsA(0);
    asm volatile("cp.async.wait_group 0;" ::: "memory");
    __syncthreads();
    for (int c = 0; c < NCHUNK; c++) {
        int cur = c & 1, nxt = cur ^ 1;
        if (c < NCHUNK - 1) { loadB(c + 1, nxt); prefA(c + 1); }
        compute(cur);
        if (c < NCHUNK - 1) {
            stsA(nxt);
            asm volatile("cp.async.wait_group 0;" ::: "memory");
        }
        __syncthreads();
    }

    // ---- row norms: half-warp (16-thread) reduction, rows (tid>>4)+16j ----
#pragma unroll
    for (int j = 0; j < 8; j++) {
#pragma unroll
        for (int o = 8; o >= 1; o >>= 1)
            rsq[j] += __shfl_xor_sync(0xffffffffu, rsq[j], o);
    }
    if ((tid & 15) == 0) {
#pragma unroll
        for (int j = 0; j < 8; j++) {
            int row = (tid >> 4) + 16 * j;
            float inv = 1.0f / fmaxf(sqrtf(rsq[j]), 1e-12f);
            sInv[row] = inv;
            g_invn[bm + row] = inv;
        }
    }
    __syncthreads();

    // ---- epilogue: |acc| * invn -> outSim ----
#pragma unroll
    for (int mi = 0; mi < 2; mi++) {
        int r0 = warpM + mi * 16 + g;
        float i0 = sInv[r0], i1 = sInv[r0 + 8];
#pragma unroll
        for (int ni = 0; ni < 11; ni++) {
            int c0 = warpN + ni * 8 + 2 * tig;
            if (c0 < KM) {
                float2 v0 = make_float2(fabsf(acc[mi][ni][0] * i0), fabsf(acc[mi][ni][1] * i0));
                float2 v1 = make_float2(fabsf(acc[mi][ni][2] * i1), fabsf(acc[mi][ni][3] * i1));
                *(float2*)&outSim[(size_t)(bm + r0) * KM + c0] = v0;
                *(float2*)&outSim[(size_t)(bm + r0 + 8) * KM + c0] = v1;
            }
        }
    }
}

// epilogue: per-row argmax/clip, conf_eff, L0 = exp(sim/eps), colsum0, counts
__global__ __launch_bounds__(256) void k_epi(const float* __restrict__ sim,
                                             const int* __restrict__ gt,
                                             const float* __restrict__ conf,
                                             float* __restrict__ outKpt) {
    __shared__ float ssim[8][KMP];
    __shared__ float scol[KM];
    __shared__ float scnt[NKPT_];
    int tid = threadIdx.x;
    if (tid < KM) scol[tid] = 0.f;
    if (tid < NKPT_) scnt[tid] = 0.f;
    __syncthreads();
    int w = tid >> 5, lane = tid & 31;
    int warpsTotal = gridDim.x * 8;
    for (int n = blockIdx.x * 8 + w; n < NN; n += warpsTotal) {
        const float* srow = sim + (size_t)n * KM;
        for (int j = lane; j < KM; j += 32) ssim[w][j] = srow[j];
        __syncwarp();
        float mx = -1.f; int bi = 17;
        if (lane < NKPT_) {
            mx = ssim[w][lane * 10];
#pragma unroll
            for (int i = 1; i < 10; i++) mx = fmaxf(mx, ssim[w][lane * 10 + i]);
            bi = lane;
        }
        float v = mx; int ii = bi;
#pragma unroll
        for (int o = 16; o > 0; o >>= 1) {
            float v2 = __shfl_xor_sync(0xffffffffu, v, o);
            int i2 = __shfl_xor_sync(0xffffffffu, ii, o);
            if (v2 > v || (v2 == v && i2 < ii)) { v = v2; ii = i2; }
        }
        int pred = ii;
        int g = gt[n];
        if (lane < NKPT_) {
            float c = fminf(fmaxf(mx, 1e-4f), 0.9999f);
            outKpt[(size_t)n * NKPT_ + lane] = c;
        }
        if (lane == 0) {
            float ce = (g == pred) ? conf[n] : 0.f;
            g_ce[n] = ce;
            atomicAdd(&scnt[g], 1.0f);
        }
        if (lane < MC) {
            float e = expf(ssim[w][g * 10 + lane] / EPS_F);
            g_L[lane * NN + n] = e;
            atomicAdd(&scol[g * 10 + lane], e);
        }
        __syncwarp();
    }
    __syncthreads();
    if (tid < KM) atomicAdd(&g_col[0][tid], scol[tid]);
    if (tid < NKPT_) atomicAdd(&g_cnt[tid], scnt[tid]);
}

// one sinkhorn iteration (col step + row step), accumulate next colsum
__global__ __launch_bounds__(256) void k_sstep(const int* __restrict__ gt, int it) {
    __shared__ float scol[KM];
    int tid = threadIdx.x;
    if (tid < KM) scol[tid] = 0.f;
    __syncthreads();
    int n = blockIdx.x * 256 + tid;
    if (n < NN) {
        int g = gt[n];
        float B = g_cnt[g];
        float Lv[MC];
        float rs = 0.f;
#pragma unroll
        for (int m = 0; m < MC; m++) {
            float l = g_L[m * NN + n];
            float t = l / (g_col[it][g * 10 + m] * 10.0f);
            Lv[m] = t; rs += t;
        }
        float den = rs * B;
#pragma unroll
        for (int m = 0; m < MC; m++) {
            float t = (rs > 0.f) ? Lv[m] / den : 0.f;
            g_L[m * NN + n] = t;
            atomicAdd(&scol[g * 10 + m], t);
        }
    }
    __syncthreads();
    if (tid < KM) atomicAdd(&g_col[it + 1][tid], scol[tid]);
}

// final iteration: idx argmax, gumbel hard assignment, compact conf list
__global__ __launch_bounds__(256) void k_s3(const int* __restrict__ gt,
                                            float* __restrict__ outTgt) {
    int n = blockIdx.x * 256 + threadIdx.x;
    if (n >= NN) return;
    int g = gt[n];
    float B = g_cnt[g];
    float t[MC];
    float rs = 0.f;
#pragma unroll
    for (int m = 0; m < MC; m++) {
        t[m] = g_L[m * NN + n] / (g_col[2][g * 10 + m] * 10.0f);
        rs += t[m];
    }
    int idx = 0; float bv = t[0];
#pragma unroll
    for (int m = 1; m < MC; m++) if (t[m] > bv) { bv = t[m]; idx = m; }
    float den = rs * B;
    unsigned kk0 = g_keys[g][0], kk1 = g_keys[g][1];
    int h = 0; float bh = -1e30f;
#pragma unroll
    for (int m = 0; m < MC; m++) {
        float a = (rs > 0.f) ? t[m] / den : 0.f;
        float Lf = a * B;
        unsigned j = (unsigned)(n * 10 + m);
        unsigned b0, b1;
        threefry2x32(kk0, kk1, 0u, j, b0, b1);
        unsigned bits = b0 ^ b1;
        float u = __uint_as_float((bits >> 9) | 0x3f800000u) - 1.0f;
        u = fmaxf(u, 1.17549435e-38f);
        float gb = -logf(-logf(u));
        float cand = Lf + gb;
        if (cand > bh) { bh = cand; h = m; }
    }
    outTgt[n] = (float)(idx + 10 * g);
    float ce = g_ce[n];
    if (ce > 0.f) {
        int p = atomicAdd(&g_nconf, 1);
        g_list[p] = n;
        g_hj[n] = h;
        g_w2[n] = ce * ce * g_invn[n];
        atomicAdd(&g_nsum[g * 10 + h], ce);
    }
}

// accumulate f[k,m,:] += ce^2 * featsN[n,:]  (warp per listed row)
__global__ __launch_bounds__(256) void k_faccum(const float* __restrict__ A,
                                                const int* __restrict__ gt) {
    int t = blockIdx.x * 256 + threadIdx.x;
    int w = t >> 5, lane = t & 31;
    int nw = (gridDim.x * 256) >> 5;
    int cnt = g_nconf;
    for (int i = w; i < cnt; i += nw) {
        int n = g_list[i];
        int g = gt[n];
        int h = g_hj[n];
        float w2 = g_w2[n];
        float* frow = &g_f[(size_t)(g * 10 + h) * DD];
        const float4* a = (const float4*)(A + (size_t)n * DD);
#pragma unroll 6
        for (int c = lane; c < DD / 4; c += 32) {
            float4 v = a[c];
            atomicAdd(&frow[4 * c + 0], w2 * v.x);
            atomicAdd(&frow[4 * c + 1], w2 * v.y);
            atomicAdd(&frow[4 * c + 2], w2 * v.z);
            atomicAdd(&frow[4 * c + 3], w2 * v.w);
        }
    }
}

// prototype EMA update + renormalization (block per (k,m))
__global__ __launch_bounds__(256) void k_newproto(float* __restrict__ outNP) {
    __shared__ float red[256];
    __shared__ float buf[DD];
    __shared__ int sup;
    int km = blockIdx.x;
    int k = km / MC;
    int tid = threadIdx.x;
    if (tid == 0) {
        float s = 0.f;
#pragma unroll
        for (int i = 0; i < MC; i++) s += g_nsum[k * MC + i];
        sup = (s > 0.f && g_nsum[km] != 0.f) ? 1 : 0;
    }
    float fs = 0.f;
    for (int d = tid; d < DD; d += 256) { float v = g_f[(size_t)km * DD + d]; fs += v * v; }
    float ftot = blockReduceSum256(fs, red);
    float finv = 1.0f / fmaxf(sqrtf(ftot), 1e-12f);
    int upd = sup;
    float vs = 0.f;
    for (int d = tid; d < DD; d += 256) {
        float pN = g_protoN[(size_t)km * DD + d];
        float fn = g_f[(size_t)km * DD + d] * finv;
        float val = upd ? (0.999f * pN + 0.001f * fn) : pN;
        buf[d] = val;
        vs += val * val;
    }
    float vtot = blockReduceSum256(vs, red);
    float vinv = 1.0f / fmaxf(sqrtf(vtot), 1e-12f);
    for (int d = tid; d < DD; d += 256)
        outNP[(size_t)km * DD + d] = buf[d] * vinv;
}

// ---------------- launch ----------------
extern "C" void kernel_launch(void* const* d_in, const int* in_sizes, int n_in,
                              void* d_out, int out_size) {
    const float* feats = (const float*)d_in[0];
    const int*   gt    = (const int*)d_in[1];
    const float* conf  = (const float*)d_in[2];
    const float* proto = (const float*)d_in[3];

    float* out  = (float*)d_out;
    float* oLog = out;                                 // N*170
    float* oTgt = oLog + (size_t)NN * KM;              // N
    float* oKpt = oTgt + NN;                           // N*17
    float* oNP  = oKpt + (size_t)NN * NKPT_;           // 170*768

    cudaFuncSetAttribute(k_gemm_mma, cudaFuncAttributeMaxDynamicSharedMemorySize, SMEM_GEMM);

    k_init<<<(KM * DD + 255) / 256, 256>>>();
    k_keys<<<1, 32>>>();
    k_pnorm<<<KM, 256>>>(proto);
    k_gemm_mma<<<NN / 128, 256, SMEM_GEMM>>>(feats, oLog);
    k_epi<<<512, 256>>>(oLog, gt, conf, oKpt);
    k_sstep<<<NN / 256, 256>>>(gt, 0);
    k_sstep<<<NN / 256, 256>>>(gt, 1);
    k_s3<<<NN / 256, 256>>>(gt, oTgt);
    k_faccum<<<512, 256>>>(feats, gt);
    k_newproto<<<KM, 256>>>(oNP);
}

// round 15
// speedup vs baseline: 3.3646x; 1.1533x over previous
#include <cuda_runtime.h>
#include <cuda_bf16.h>
#include <math.h>
#include <stdint.h>
#include <stddef.h>

// ---------------- problem constants ----------------
#define NN    131072
#define DD    768
#define NKPT_ 17
#define MC    10
#define KM    170          // NKPT*M
#define KMP   176          // padded column count
#define EPS_F 0.05f
#define KC    64           // K chunk
#define NCHUNK 12          // DD/KC

// GEMM smem: rows padded to 72 halves (144 B) -> conflict-free 32b frag loads
#define PADK   72
#define ROWB   (PADK * 2)                // 144 bytes per smem row
#define STG_A  (128 * ROWB)              // 18432 B per A buffer
#define STG_B  (176 * ROWB)              // 25344 B per B buffer
#define OFF_AHI 0
#define OFF_ALO STG_A
#define OFF_BHI (2 * STG_A)
#define OFF_BLO (2 * STG_A + STG_B)
#define STAGE   (2 * STG_A + 2 * STG_B)  // 87552 B
#define BUFW    180                      // epi smem stride (floats)
#define SMEM_GEMM (2 * STAGE + 4096)

// ---------------- device scratch (no allocations allowed) ----------------
__device__ __nv_bfloat16 g_Bhi[KMP * DD];  // normalized protos hi (rows 170..175 zero)
__device__ __nv_bfloat16 g_Blo[KMP * DD];  // normalized protos lo
__device__ float    g_protoN[KM * DD];     // normalized prototypes fp32 (for EMA)
__device__ float    g_invn[NN];            // 1 / max(||feats_n||, 1e-12)
__device__ float    g_L[MC * NN];          // sinkhorn state, column-major [m][n]
__device__ float    g_ce[NN];              // conf_eff
__device__ float    g_col[3][KM];          // column sums per iteration
__device__ float    g_cnt[NKPT_];          // member counts B_k
__device__ float    g_nsum[KM];            // n[k,m]
__device__ float    g_f[KM * DD];          // f accumulator
__device__ unsigned g_keys[NKPT_][2];      // per-class threefry keys
__device__ int      g_list[NN];
__device__ int      g_hj[NN];
__device__ float    g_w2[NN];
__device__ int      g_nconf;

// ---------------- helpers ----------------
__device__ __forceinline__ uint32_t smem_u32(const void* p) {
    uint32_t a;
    asm("{ .reg .u64 t; cvta.to.shared.u64 t, %1; cvt.u32.u64 %0, t; }" : "=r"(a) : "l"(p));
    return a;
}

__device__ __forceinline__ unsigned lds32(uint32_t a) {
    unsigned v;
    asm volatile("ld.shared.b32 %0, [%1];" : "=r"(v) : "r"(a));
    return v;
}

__device__ __forceinline__ void cpasync8(uint32_t dst, const void* src) {
    asm volatile("cp.async.ca.shared.global [%0], [%1], 8;" :: "r"(dst), "l"(src) : "memory");
}

__device__ __forceinline__ void mma16816(float* d, const unsigned* a, const unsigned* b) {
    asm volatile(
        "mma.sync.aligned.m16n8k16.row.col.f32.bf16.bf16.f32 "
        "{%0,%1,%2,%3}, {%4,%5,%6,%7}, {%8,%9}, {%0,%1,%2,%3};"
        : "+f"(d[0]), "+f"(d[1]), "+f"(d[2]), "+f"(d[3])
        : "r"(a[0]), "r"(a[1]), "r"(a[2]), "r"(a[3]), "r"(b[0]), "r"(b[1]));
}

__device__ __forceinline__ void split2(float x, float y, unsigned& h, unsigned& l) {
    __nv_bfloat16 hx = __float2bfloat16(x), hy = __float2bfloat16(y);
    float rx = x - __bfloat162float(hx), ry = y - __bfloat162float(hy);
    __nv_bfloat16 lx = __float2bfloat16(rx), ly = __float2bfloat16(ry);
    h = (unsigned)__bfloat16_as_ushort(hx) | ((unsigned)__bfloat16_as_ushort(hy) << 16);
    l = (unsigned)__bfloat16_as_ushort(lx) | ((unsigned)__bfloat16_as_ushort(ly) << 16);
}

// ---------------- threefry2x32 (matches JAX) ----------------
__device__ __forceinline__ void threefry2x32(unsigned k0, unsigned k1,
                                             unsigned x0, unsigned x1,
                                             unsigned& o0, unsigned& o1) {
    unsigned ks2 = k0 ^ k1 ^ 0x1BD11BDAu;
    x0 += k0; x1 += k1;
#define TFR(r) { x0 += x1; x1 = (x1 << (r)) | (x1 >> (32 - (r))); x1 ^= x0; }
    TFR(13) TFR(15) TFR(26) TFR(6)  x0 += k1;  x1 += ks2 + 1u;
    TFR(17) TFR(29) TFR(16) TFR(24) x0 += ks2; x1 += k0 + 2u;
    TFR(13) TFR(15) TFR(26) TFR(6)  x0 += k0;  x1 += k1 + 3u;
    TFR(17) TFR(29) TFR(16) TFR(24) x0 += k1;  x1 += ks2 + 4u;
    TFR(13) TFR(15) TFR(26) TFR(6)  x0 += ks2; x1 += k0 + 5u;
#undef TFR
    o0 = x0; o1 = x1;
}

__device__ __forceinline__ float blockReduceSum256(float v, float* red) {
    int tid = threadIdx.x;
    red[tid] = v;
    __syncthreads();
#pragma unroll
    for (int s = 128; s > 0; s >>= 1) {
        if (tid < s) red[tid] += red[tid + s];
        __syncthreads();
    }
    float r = red[0];
    __syncthreads();
    return r;
}

// ---------------- kernels ----------------

__global__ void k_init() {
    int i = blockIdx.x * 256 + threadIdx.x;
    if (i < KM * DD) g_f[i] = 0.f;
    if (i < 3 * KM)  ((float*)g_col)[i] = 0.f;
    if (i < KM)      g_nsum[i] = 0.f;
    if (i < NKPT_)   g_cnt[i] = 0.f;
    if (i == 0)      g_nconf = 0;
    if (i < NKPT_) {
        unsigned a, b;
        threefry2x32(0u, 42u, 0u, (unsigned)i, a, b);
        g_keys[i][0] = a; g_keys[i][1] = b;
    }
}

// normalize prototypes -> fp32 + bf16 hi/lo
__global__ __launch_bounds__(256) void k_pnorm(const float* __restrict__ P) {
    __shared__ float red[256];
    int j = blockIdx.x;   // 0..169
    int tid = threadIdx.x;
    const float* p = P + (size_t)j * DD;
    float s = 0.f;
    for (int d = tid; d < DD; d += 256) { float x = p[d]; s += x * x; }
    float tot = blockReduceSum256(s, red);
    float inv = 1.0f / fmaxf(sqrtf(tot), 1e-12f);
    for (int d = tid; d < DD; d += 256) {
        float v = p[d] * inv;
        g_protoN[(size_t)j * DD + d] = v;
        __nv_bfloat16 h = __float2bfloat16(v);
        __nv_bfloat16 l = __float2bfloat16(v - __bfloat162float(h));
        g_Bhi[(size_t)j * DD + d] = h;
        g_Blo[(size_t)j * DD + d] = l;
    }
}

// ---------------- tensor-core GEMM (mma.sync, bf16x3) + fused epilogue ----------------
// CTA tile 128 x 176, 512 threads = 16 warps (8M x 2N), warp tile 16 x 88.
// Fused: row inv-norms, |sim| logits, per-row argmax/clip, conf_eff,
//        L0 = exp(sim/eps), colsum0, class counts.
__global__ void __launch_bounds__(512, 1) k_gemm_mma(const float* __restrict__ A,
                                                     const int* __restrict__ gt,
                                                     const float* __restrict__ conf,
                                                     float* __restrict__ outSim,
                                                     float* __restrict__ outKpt) {
    extern __shared__ char smem[];
    float* sInv = (float*)(smem + 2 * STAGE);                 // 128 floats
    float* scol = sInv + 128;                                 // 170
    float* scnt = scol + KM;                                  // 17
    float* buf  = (float*)smem;                               // epi overlay [128][BUFW]
    const uint32_t sbase = smem_u32(smem);
    const int tid = threadIdx.x;
    const int wid = tid >> 5, lane = tid & 31;
    const int gq = lane >> 2, tig = lane & 3;
    const int bm = blockIdx.x * 128;
    const int warpM = (wid >> 1) * 16;
    const int warpN = (wid & 1) * 88;

    if (tid < KM) scol[tid] = 0.f;
    if (tid < NKPT_) scnt[tid] = 0.f;

    float rsq[4];
    float acc[11][4];
    float4 pref[4];
#pragma unroll
    for (int j = 0; j < 4; j++) rsq[j] = 0.f;
#pragma unroll
    for (int ni = 0; ni < 11; ni++)
#pragma unroll
        for (int q = 0; q < 4; q++) acc[ni][q] = 0.f;

    auto loadB = [&](int c, int st) {
        const int k0 = c * KC;
        uint32_t dhi = sbase + (uint32_t)(st * STAGE + OFF_BHI);
        uint32_t dlo = sbase + (uint32_t)(st * STAGE + OFF_BLO);
#pragma unroll
        for (int i = 0; i < 11; i++) {
            int id = tid + 512 * i;      // 0..5631
            int t2 = (id < 2816) ? id : id - 2816;
            int row = t2 >> 4, col = (t2 & 15) * 4;
            uint32_t off = (uint32_t)(row * ROWB + col * 2);
            if (id < 2816)
                cpasync8(dhi + off, g_Bhi + (size_t)row * DD + k0 + col);
            else
                cpasync8(dlo + off, g_Blo + (size_t)row * DD + k0 + col);
        }
        asm volatile("cp.async.commit_group;" ::: "memory");
    };
    auto prefA = [&](int c) {
        const int k0 = c * KC;
#pragma unroll
        for (int j = 0; j < 4; j++) {
            int id = tid + 512 * j;
            int row = id >> 4, col = (id & 15) * 4;
            pref[j] = *(const float4*)(A + (size_t)(bm + row) * DD + k0 + col);
        }
    };
    auto stsA = [&](int st) {
        char* base = smem + st * STAGE;
        __nv_bfloat16* ahi = (__nv_bfloat16*)(base + OFF_AHI);
        __nv_bfloat16* alo = (__nv_bfloat16*)(base + OFF_ALO);
#pragma unroll
        for (int j = 0; j < 4; j++) {
            int id = tid + 512 * j;
            int row = id >> 4, col = (id & 15) * 4;
            float4 v = pref[j];
            rsq[j] += v.x * v.x + v.y * v.y + v.z * v.z + v.w * v.w;
            unsigned h01, l01, h23, l23;
            split2(v.x, v.y, h01, l01);
            split2(v.z, v.w, h23, l23);
            *(uint2*)(ahi + row * PADK + col) = make_uint2(h01, h23);
            *(uint2*)(alo + row * PADK + col) = make_uint2(l01, l23);
        }
    };
    auto compute = [&](int st) {
        uint32_t aHi = sbase + (uint32_t)(st * STAGE + OFF_AHI);
        uint32_t aLo = aHi + STG_A;
        uint32_t bHi = sbase + (uint32_t)(st * STAGE + OFF_BHI);
        uint32_t bLo = bHi + STG_B;
        const uint32_t arow = (uint32_t)((warpM + gq) * ROWB);
#pragma unroll
        for (int ks = 0; ks < 4; ks++) {
            const uint32_t kb = (uint32_t)((ks * 16 + 2 * tig) * 2);
            unsigned af[4], bf[11][2];
            // B hi frags
#pragma unroll
            for (int ni = 0; ni < 11; ni++) {
                uint32_t r0 = bHi + (uint32_t)((warpN + ni * 8 + gq) * ROWB) + kb;
                bf[ni][0] = lds32(r0);
                bf[ni][1] = lds32(r0 + 16);
            }
            // pass 0: Ahi * Bhi
            {
                uint32_t r0 = aHi + arow + kb;
                af[0] = lds32(r0); af[1] = lds32(r0 + 8 * ROWB);
                af[2] = lds32(r0 + 16); af[3] = lds32(r0 + 8 * ROWB + 16);
            }
#pragma unroll
            for (int ni = 0; ni < 11; ni++) mma16816(acc[ni], af, bf[ni]);
            // pass 1: Alo * Bhi
            {
                uint32_t r0 = aLo + arow + kb;
                af[0] = lds32(r0); af[1] = lds32(r0 + 8 * ROWB);
                af[2] = lds32(r0 + 16); af[3] = lds32(r0 + 8 * ROWB + 16);
            }
#pragma unroll
            for (int ni = 0; ni < 11; ni++) mma16816(acc[ni], af, bf[ni]);
            // pass 2: Ahi * Blo
            {
                uint32_t r0 = aHi + arow + kb;
                af[0] = lds32(r0); af[1] = lds32(r0 + 8 * ROWB);
                af[2] = lds32(r0 + 16); af[3] = lds32(r0 + 8 * ROWB + 16);
            }
#pragma unroll
            for (int ni = 0; ni < 11; ni++) {
                uint32_t r0 = bLo + (uint32_t)((warpN + ni * 8 + gq) * ROWB) + kb;
                bf[ni][0] = lds32(r0);
                bf[ni][1] = lds32(r0 + 16);
            }
#pragma unroll
            for (int ni = 0; ni < 11; ni++) mma16816(acc[ni], af, bf[ni]);
        }
    };

    // ---- pipeline ----
    loadB(0, 0);
    prefA(0);
    stsA(0);
    asm volatile("cp.async.wait_group 0;" ::: "memory");
    __syncthreads();
    for (int c = 0; c < NCHUNK; c++) {
        int cur = c & 1, nxt = cur ^ 1;
        if (c < NCHUNK - 1) { loadB(c + 1, nxt); prefA(c + 1); }
        compute(cur);
        if (c < NCHUNK - 1) {
            stsA(nxt);
            asm volatile("cp.async.wait_group 0;" ::: "memory");
        }
        __syncthreads();
    }

    // ---- row norms: 16-thread groups share a row ----
#pragma unroll
    for (int j = 0; j < 4; j++) {
#pragma unroll
        for (int o = 8; o >= 1; o >>= 1)
            rsq[j] += __shfl_xor_sync(0xffffffffu, rsq[j], o);
    }
    if ((tid & 15) == 0) {
#pragma unroll
        for (int j = 0; j < 4; j++) {
            int row = (tid >> 4) + 32 * j;
            float inv = 1.0f / fmaxf(sqrtf(rsq[j]), 1e-12f);
            sInv[row] = inv;
            g_invn[bm + row] = inv;
        }
    }
    __syncthreads();

    // ---- |acc| * invn -> smem buf ----
    {
        int r0 = warpM + gq;
        float i0 = sInv[r0], i1 = sInv[r0 + 8];
#pragma unroll
        for (int ni = 0; ni < 11; ni++) {
            int c0 = warpN + ni * 8 + 2 * tig;
            buf[r0 * BUFW + c0]       = fabsf(acc[ni][0] * i0);
            buf[r0 * BUFW + c0 + 1]   = fabsf(acc[ni][1] * i0);
            buf[(r0 + 8) * BUFW + c0]     = fabsf(acc[ni][2] * i1);
            buf[(r0 + 8) * BUFW + c0 + 1] = fabsf(acc[ni][3] * i1);
        }
    }
    __syncthreads();

    // ---- fused epilogue: each warp handles 8 rows ----
    for (int rr = 0; rr < 8; rr++) {
        int row = wid * 8 + rr;
        int n = bm + row;
        float mx = -1.f; int bi = NKPT_;
        if (lane < NKPT_) {
            const float* br = buf + row * BUFW + lane * 10;
            mx = br[0];
#pragma unroll
            for (int i = 1; i < 10; i++) mx = fmaxf(mx, br[i]);
            bi = lane;
        }
        float v = mx; int ii = bi;
#pragma unroll
        for (int o = 16; o > 0; o >>= 1) {
            float v2 = __shfl_xor_sync(0xffffffffu, v, o);
            int i2 = __shfl_xor_sync(0xffffffffu, ii, o);
            if (v2 > v || (v2 == v && i2 < ii)) { v = v2; ii = i2; }
        }
        int pred = ii;
        int gcls = gt[n];
        if (lane < NKPT_)
            outKpt[(size_t)n * NKPT_ + lane] = fminf(fmaxf(mx, 1e-4f), 0.9999f);
        if (lane == 0) {
            float ce = (gcls == pred) ? conf[n] : 0.f;
            g_ce[n] = ce;
            atomicAdd(&scnt[gcls], 1.0f);
        }
        if (lane < MC) {
            float e = expf(buf[row * BUFW + gcls * 10 + lane] / EPS_F);
            g_L[lane * NN + n] = e;
            atomicAdd(&scol[gcls * 10 + lane], e);
        }
        __syncwarp();
    }

    // ---- logits store (coalesced within rows) ----
    for (int rr = 0; rr < 8; rr++) {
        int row = wid * 8 + rr;
        for (int c = lane; c < KM; c += 32)
            outSim[(size_t)(bm + row) * KM + c] = buf[row * BUFW + c];
    }

    __syncthreads();
    if (tid < KM) atomicAdd(&g_col[0][tid], scol[tid]);
    if (tid < NKPT_) atomicAdd(&g_cnt[tid], scnt[tid]);
}

// one sinkhorn iteration (col step + row step), accumulate next colsum
__global__ __launch_bounds__(256) void k_sstep(const int* __restrict__ gt, int it) {
    __shared__ float scol[KM];
    int tid = threadIdx.x;
    if (tid < KM) scol[tid] = 0.f;
    __syncthreads();
    int n = blockIdx.x * 256 + tid;
    if (n < NN) {
        int g = gt[n];
        float B = g_cnt[g];
        float Lv[MC];
        float rs = 0.f;
#pragma unroll
        for (int m = 0; m < MC; m++) {
            float l = g_L[m * NN + n];
            float t = l / (g_col[it][g * 10 + m] * 10.0f);
            Lv[m] = t; rs += t;
        }
        float den = rs * B;
#pragma unroll
        for (int m = 0; m < MC; m++) {
            float t = (rs > 0.f) ? Lv[m] / den : 0.f;
            g_L[m * NN + n] = t;
            atomicAdd(&scol[g * 10 + m], t);
        }
    }
    __syncthreads();
    if (tid < KM) atomicAdd(&g_col[it + 1][tid], scol[tid]);
}

// final iteration: idx argmax, gumbel hard assignment, compact conf list
__global__ __launch_bounds__(256) void k_s3(const int* __restrict__ gt,
                                            float* __restrict__ outTgt) {
    int n = blockIdx.x * 256 + threadIdx.x;
    if (n >= NN) return;
    int g = gt[n];
    float B = g_cnt[g];
    float t[MC];
    float rs = 0.f;
#pragma unroll
    for (int m = 0; m < MC; m++) {
        t[m] = g_L[m * NN + n] / (g_col[2][g * 10 + m] * 10.0f);
        rs += t[m];
    }
    int idx = 0; float bv = t[0];
#pragma unroll
    for (int m = 1; m < MC; m++) if (t[m] > bv) { bv = t[m]; idx = m; }
    float den = rs * B;
    unsigned kk0 = g_keys[g][0], kk1 = g_keys[g][1];
    int h = 0; float bh = -1e30f;
#pragma unroll
    for (int m = 0; m < MC; m++) {
        float a = (rs > 0.f) ? t[m] / den : 0.f;
        float Lf = a * B;
        unsigned j = (unsigned)(n * 10 + m);
        unsigned b0, b1;
        threefry2x32(kk0, kk1, 0u, j, b0, b1);
        unsigned bits = b0 ^ b1;
        float u = __uint_as_float((bits >> 9) | 0x3f800000u) - 1.0f;
        u = fmaxf(u, 1.17549435e-38f);
        float gb = -logf(-logf(u));
        float cand = Lf + gb;
        if (cand > bh) { bh = cand; h = m; }
    }
    outTgt[n] = (float)(idx + 10 * g);
    float ce = g_ce[n];
    if (ce > 0.f) {
        int p = atomicAdd(&g_nconf, 1);
        g_list[p] = n;
        g_hj[n] = h;
        g_w2[n] = ce * ce * g_invn[n];
        atomicAdd(&g_nsum[g * 10 + h], ce);
    }
}

// accumulate f[k,m,:] += ce^2 * featsN[n,:]  (warp per listed row)
__global__ __launch_bounds__(256) void k_faccum(const float* __restrict__ A,
                                                const int* __restrict__ gt) {
    int t = blockIdx.x * 256 + threadIdx.x;
    int w = t >> 5, lane = t & 31;
    int nw = (gridDim.x * 256) >> 5;
    int cnt = g_nconf;
    for (int i = w; i < cnt; i += nw) {
        int n = g_list[i];
        int g = gt[n];
        int h = g_hj[n];
        float w2 = g_w2[n];
        float* frow = &g_f[(size_t)(g * 10 + h) * DD];
        const float4* a = (const float4*)(A + (size_t)n * DD);
#pragma unroll 6
        for (int c = lane; c < DD / 4; c += 32) {
            float4 v = a[c];
            atomicAdd(&frow[4 * c + 0], w2 * v.x);
            atomicAdd(&frow[4 * c + 1], w2 * v.y);
            atomicAdd(&frow[4 * c + 2], w2 * v.z);
            atomicAdd(&frow[4 * c + 3], w2 * v.w);
        }
    }
}

// prototype EMA update + renormalization (block per (k,m))
__global__ __launch_bounds__(256) void k_newproto(float* __restrict__ outNP) {
    __shared__ float red[256];
    __shared__ float buf[DD];
    __shared__ int sup;
    int km = blockIdx.x;
    int k = km / MC;
    int tid = threadIdx.x;
    if (tid == 0) {
        float s = 0.f;
#pragma unroll
        for (int i = 0; i < MC; i++) s += g_nsum[k * MC + i];
        sup = (s > 0.f && g_nsum[km] != 0.f) ? 1 : 0;
    }
    float fs = 0.f;
    for (int d = tid; d < DD; d += 256) { float v = g_f[(size_t)km * DD + d]; fs += v * v; }
    float ftot = blockReduceSum256(fs, red);
    float finv = 1.0f / fmaxf(sqrtf(ftot), 1e-12f);
    int upd = sup;
    float vs = 0.f;
    for (int d = tid; d < DD; d += 256) {
        float pN = g_protoN[(size_t)km * DD + d];
        float fn = g_f[(size_t)km * DD + d] * finv;
        float val = upd ? (0.999f * pN + 0.001f * fn) : pN;
        buf[d] = val;
        vs += val * val;
    }
    float vtot = blockReduceSum256(vs, red);
    float vinv = 1.0f / fmaxf(sqrtf(vtot), 1e-12f);
    for (int d = tid; d < DD; d += 256)
        outNP[(size_t)km * DD + d] = buf[d] * vinv;
}

// ---------------- launch ----------------
extern "C" void kernel_launch(void* const* d_in, const int* in_sizes, int n_in,
                              void* d_out, int out_size) {
    const float* feats = (const float*)d_in[0];
    const int*   gt    = (const int*)d_in[1];
    const float* conf  = (const float*)d_in[2];
    const float* proto = (const float*)d_in[3];

    float* out  = (float*)d_out;
    float* oLog = out;                                 // N*170
    float* oTgt = oLog + (size_t)NN * KM;              // N
    float* oKpt = oTgt + NN;                           // N*17
    float* oNP  = oKpt + (size_t)NN * NKPT_;           // 170*768

    cudaFuncSetAttribute(k_gemm_mma, cudaFuncAttributeMaxDynamicSharedMemorySize, SMEM_GEMM);

    k_init<<<(KM * DD + 255) / 256, 256>>>();
    k_pnorm<<<KM, 256>>>(proto);
    k_gemm_mma<<<NN / 128, 512, SMEM_GEMM>>>(feats, gt, conf, oLog, oKpt);
    k_sstep<<<NN / 256, 256>>>(gt, 0);
    k_sstep<<<NN / 256, 256>>>(gt, 1);
    k_s3<<<NN / 256, 256>>>(gt, oTgt);
    k_faccum<<<512, 256>>>(feats, gt);
    k_newproto<<<KM, 256>>>(oNP);
}

// round 16
// speedup vs baseline: 3.5861x; 1.0658x over previous
#include <cuda_runtime.h>
#include <cuda_bf16.h>
#include <math.h>
#include <stdint.h>
#include <stddef.h>

// ---------------- problem constants ----------------
#define NN    131072
#define DD    768
#define NKPT_ 17
#define MC    10
#define KM    170          // NKPT*M
#define KMP   176          // padded column count
#define EPS_F 0.05f
#define KC    64           // K chunk
#define NCHUNK 12          // DD/KC

// GEMM smem: rows padded to 72 halves (144 B) -> conflict-free ldmatrix
#define PADK   72
#define ROWB   (PADK * 2)                // 144 bytes per smem row
#define STG_A  (128 * ROWB)              // 18432 B per A buffer
#define STG_B  (176 * ROWB)              // 25344 B per B buffer
#define OFF_AHI 0
#define OFF_ALO STG_A
#define OFF_BHI (2 * STG_A)
#define OFF_BLO (2 * STG_A + STG_B)
#define STAGE   (2 * STG_A + 2 * STG_B)  // 87552 B
#define BUFW    180                      // epi smem stride (floats)
#define SMEM_GEMM (2 * STAGE + 4096)

// ---------------- device scratch (no allocations allowed) ----------------
__device__ __nv_bfloat16 g_Bhi[KMP * DD];  // normalized protos hi (rows 170..175 zero)
__device__ __nv_bfloat16 g_Blo[KMP * DD];  // normalized protos lo
__device__ float    g_protoN[KM * DD];     // normalized prototypes fp32 (for EMA)
__device__ float    g_invn[NN];            // 1 / max(||feats_n||, 1e-12)
__device__ float    g_L[MC * NN];          // initial e = exp(sim/eps), column-major [m][n]
__device__ float    g_ce[NN];              // conf_eff
__device__ float    g_col[3][KM];          // column sums per iteration
__device__ float    g_cnt[NKPT_];          // member counts B_k
__device__ float    g_nsum[KM];            // n[k,m]
__device__ float    g_f[KM * DD];          // f accumulator
__device__ unsigned g_keys[NKPT_][2];      // per-class threefry keys
__device__ int      g_list[NN];
__device__ int      g_hj[NN];
__device__ float    g_w2[NN];
__device__ int      g_nconf;

// ---------------- helpers ----------------
__device__ __forceinline__ uint32_t smem_u32(const void* p) {
    uint32_t a;
    asm("{ .reg .u64 t; cvta.to.shared.u64 t, %1; cvt.u32.u64 %0, t; }" : "=r"(a) : "l"(p));
    return a;
}

__device__ __forceinline__ void cpasync8(uint32_t dst, const void* src) {
    asm volatile("cp.async.ca.shared.global [%0], [%1], 8;" :: "r"(dst), "l"(src) : "memory");
}

__device__ __forceinline__ void ldsm_x4(unsigned* r, uint32_t addr) {
    asm volatile("ldmatrix.sync.aligned.m8n8.x4.shared.b16 {%0,%1,%2,%3}, [%4];"
                 : "=r"(r[0]), "=r"(r[1]), "=r"(r[2]), "=r"(r[3]) : "r"(addr));
}

__device__ __forceinline__ void ldsm_x2(unsigned* r, uint32_t addr) {
    asm volatile("ldmatrix.sync.aligned.m8n8.x2.shared.b16 {%0,%1}, [%2];"
                 : "=r"(r[0]), "=r"(r[1]) : "r"(addr));
}

__device__ __forceinline__ void mma16816(float* d, const unsigned* a, const unsigned* b) {
    asm volatile(
        "mma.sync.aligned.m16n8k16.row.col.f32.bf16.bf16.f32 "
        "{%0,%1,%2,%3}, {%4,%5,%6,%7}, {%8,%9}, {%0,%1,%2,%3};"
        : "+f"(d[0]), "+f"(d[1]), "+f"(d[2]), "+f"(d[3])
        : "r"(a[0]), "r"(a[1]), "r"(a[2]), "r"(a[3]), "r"(b[0]), "r"(b[1]));
}

__device__ __forceinline__ void split2(float x, float y, unsigned& h, unsigned& l) {
    __nv_bfloat16 hx = __float2bfloat16(x), hy = __float2bfloat16(y);
    float rx = x - __bfloat162float(hx), ry = y - __bfloat162float(hy);
    __nv_bfloat16 lx = __float2bfloat16(rx), ly = __float2bfloat16(ry);
    h = (unsigned)__bfloat16_as_ushort(hx) | ((unsigned)__bfloat16_as_ushort(hy) << 16);
    l = (unsigned)__bfloat16_as_ushort(lx) | ((unsigned)__bfloat16_as_ushort(ly) << 16);
}

// ---------------- threefry2x32 (matches JAX) ----------------
__device__ __forceinline__ void threefry2x32(unsigned k0, unsigned k1,
                                             unsigned x0, unsigned x1,
                                             unsigned& o0, unsigned& o1) {
    unsigned ks2 = k0 ^ k1 ^ 0x1BD11BDAu;
    x0 += k0; x1 += k1;
#define TFR(r) { x0 += x1; x1 = (x1 << (r)) | (x1 >> (32 - (r))); x1 ^= x0; }
    TFR(13) TFR(15) TFR(26) TFR(6)  x0 += k1;  x1 += ks2 + 1u;
    TFR(17) TFR(29) TFR(16) TFR(24) x0 += ks2; x1 += k0 + 2u;
    TFR(13) TFR(15) TFR(26) TFR(6)  x0 += k0;  x1 += k1 + 3u;
    TFR(17) TFR(29) TFR(16) TFR(24) x0 += k1;  x1 += ks2 + 4u;
    TFR(13) TFR(15) TFR(26) TFR(6)  x0 += ks2; x1 += k0 + 5u;
#undef TFR
    o0 = x0; o1 = x1;
}

__device__ __forceinline__ float blockReduceSum256(float v, float* red) {
    int tid = threadIdx.x;
    red[tid] = v;
    __syncthreads();
#pragma unroll
    for (int s = 128; s > 0; s >>= 1) {
        if (tid < s) red[tid] += red[tid + s];
        __syncthreads();
    }
    float r = red[0];
    __syncthreads();
    return r;
}

// ---------------- kernels ----------------

__global__ void k_init() {
    int i = blockIdx.x * 256 + threadIdx.x;
    if (i < KM * DD) g_f[i] = 0.f;
    if (i < 3 * KM)  ((float*)g_col)[i] = 0.f;
    if (i < KM)      g_nsum[i] = 0.f;
    if (i < NKPT_)   g_cnt[i] = 0.f;
    if (i == 0)      g_nconf = 0;
    if (i < NKPT_) {
        unsigned a, b;
        threefry2x32(0u, 42u, 0u, (unsigned)i, a, b);
        g_keys[i][0] = a; g_keys[i][1] = b;
    }
}

// normalize prototypes -> fp32 + bf16 hi/lo
__global__ __launch_bounds__(256) void k_pnorm(const float* __restrict__ P) {
    __shared__ float red[256];
    int j = blockIdx.x;   // 0..169
    int tid = threadIdx.x;
    const float* p = P + (size_t)j * DD;
    float s = 0.f;
    for (int d = tid; d < DD; d += 256) { float x = p[d]; s += x * x; }
    float tot = blockReduceSum256(s, red);
    float inv = 1.0f / fmaxf(sqrtf(tot), 1e-12f);
    for (int d = tid; d < DD; d += 256) {
        float v = p[d] * inv;
        g_protoN[(size_t)j * DD + d] = v;
        __nv_bfloat16 h = __float2bfloat16(v);
        __nv_bfloat16 l = __float2bfloat16(v - __bfloat162float(h));
        g_Bhi[(size_t)j * DD + d] = h;
        g_Blo[(size_t)j * DD + d] = l;
    }
}

// ---------------- tensor-core GEMM (mma.sync + ldmatrix, bf16x3) + fused epilogue ----
// CTA tile 128 x 176, 512 threads = 16 warps (8M x 2N), warp tile 16 x 88.
__global__ void __launch_bounds__(512, 1) k_gemm_mma(const float* __restrict__ A,
                                                     const int* __restrict__ gt,
                                                     const float* __restrict__ conf,
                                                     float* __restrict__ outSim,
                                                     float* __restrict__ outKpt) {
    extern __shared__ char smem[];
    float* sInv = (float*)(smem + 2 * STAGE);                 // 128 floats
    float* scol = sInv + 128;                                 // 170
    float* scnt = scol + KM;                                  // 17
    float* buf  = (float*)smem;                               // epi overlay [128][BUFW]
    const uint32_t sbase = smem_u32(smem);
    const int tid = threadIdx.x;
    const int wid = tid >> 5, lane = tid & 31;
    const int gq = lane >> 2, tig = lane & 3;
    const int bm = blockIdx.x * 128;
    const int warpM = (wid >> 1) * 16;
    const int warpN = (wid & 1) * 88;

    if (tid < KM) scol[tid] = 0.f;
    if (tid < NKPT_) scnt[tid] = 0.f;

    // ldmatrix per-lane row offsets (within a tile, bytes)
    const uint32_t aRowOff = (uint32_t)((warpM + (lane & 15)) * ROWB + ((lane & 16) ? 16 : 0));
    const uint32_t bRowOff4 = (uint32_t)(((lane & 7) + ((lane & 16) ? 8 : 0)) * ROWB +
                                         ((lane & 8) ? 16 : 0));
    const uint32_t bRowOff2 = (uint32_t)((lane & 7) * ROWB + ((lane & 8) ? 16 : 0));

    float rsq[4];
    float acc[11][4];
    float4 pref[4];
#pragma unroll
    for (int j = 0; j < 4; j++) rsq[j] = 0.f;
#pragma unroll
    for (int ni = 0; ni < 11; ni++)
#pragma unroll
        for (int q = 0; q < 4; q++) acc[ni][q] = 0.f;

    auto loadB = [&](int c, int st) {
        const int k0 = c * KC;
        uint32_t dhi = sbase + (uint32_t)(st * STAGE + OFF_BHI);
        uint32_t dlo = sbase + (uint32_t)(st * STAGE + OFF_BLO);
#pragma unroll
        for (int i = 0; i < 11; i++) {
            int id = tid + 512 * i;      // 0..5631
            int t2 = (id < 2816) ? id : id - 2816;
            int row = t2 >> 4, col = (t2 & 15) * 4;
            uint32_t off = (uint32_t)(row * ROWB + col * 2);
            if (id < 2816)
                cpasync8(dhi + off, g_Bhi + (size_t)row * DD + k0 + col);
            else
                cpasync8(dlo + off, g_Blo + (size_t)row * DD + k0 + col);
        }
        asm volatile("cp.async.commit_group;" ::: "memory");
    };
    auto prefA = [&](int c) {
        const int k0 = c * KC;
#pragma unroll
        for (int j = 0; j < 4; j++) {
            int id = tid + 512 * j;
            int row = id >> 4, col = (id & 15) * 4;
            pref[j] = *(const float4*)(A + (size_t)(bm + row) * DD + k0 + col);
        }
    };
    auto stsA = [&](int st) {
        char* base = smem + st * STAGE;
        __nv_bfloat16* ahi = (__nv_bfloat16*)(base + OFF_AHI);
        __nv_bfloat16* alo = (__nv_bfloat16*)(base + OFF_ALO);
#pragma unroll
        for (int j = 0; j < 4; j++) {
            int id = tid + 512 * j;
            int row = id >> 4, col = (id & 15) * 4;
            float4 v = pref[j];
            rsq[j] += v.x * v.x + v.y * v.y + v.z * v.z + v.w * v.w;
            unsigned h01, l01, h23, l23;
            split2(v.x, v.y, h01, l01);
            split2(v.z, v.w, h23, l23);
            *(uint2*)(ahi + row * PADK + col) = make_uint2(h01, h23);
            *(uint2*)(alo + row * PADK + col) = make_uint2(l01, l23);
        }
    };
    auto compute = [&](int st) {
        const uint32_t aHi = sbase + (uint32_t)(st * STAGE + OFF_AHI);
        const uint32_t aLo = aHi + STG_A;
        const uint32_t bHi = sbase + (uint32_t)(st * STAGE + OFF_BHI);
        const uint32_t bLo = bHi + STG_B;
#pragma unroll
        for (int ks = 0; ks < 4; ks++) {
            const uint32_t kbase = (uint32_t)(ks * 32);
            unsigned ah[4], al[4], bb[22];
            ldsm_x4(ah, aHi + aRowOff + kbase);
            ldsm_x4(al, aLo + aRowOff + kbase);
#pragma unroll
            for (int p = 0; p < 5; p++)
                ldsm_x4(&bb[4 * p], bHi + (uint32_t)((warpN + p * 16) * ROWB) + bRowOff4 + kbase);
            ldsm_x2(&bb[20], bHi + (uint32_t)((warpN + 80) * ROWB) + bRowOff2 + kbase);
            // pass 0: Ahi*Bhi, pass 1: Alo*Bhi
#pragma unroll
            for (int ni = 0; ni < 11; ni++) mma16816(acc[ni], ah, &bb[2 * ni]);
#pragma unroll
            for (int ni = 0; ni < 11; ni++) mma16816(acc[ni], al, &bb[2 * ni]);
            // reload B as lo, pass 2: Ahi*Blo (A-hi frags reused)
#pragma unroll
            for (int p = 0; p < 5; p++)
                ldsm_x4(&bb[4 * p], bLo + (uint32_t)((warpN + p * 16) * ROWB) + bRowOff4 + kbase);
            ldsm_x2(&bb[20], bLo + (uint32_t)((warpN + 80) * ROWB) + bRowOff2 + kbase);
#pragma unroll
            for (int ni = 0; ni < 11; ni++) mma16816(acc[ni], ah, &bb[2 * ni]);
        }
    };

    // ---- pipeline ----
    loadB(0, 0);
    prefA(0);
    stsA(0);
    asm volatile("cp.async.wait_group 0;" ::: "memory");
    __syncthreads();
    for (int c = 0; c < NCHUNK; c++) {
        int cur = c & 1, nxt = cur ^ 1;
        if (c < NCHUNK - 1) { loadB(c + 1, nxt); prefA(c + 1); }
        compute(cur);
        if (c < NCHUNK - 1) {
            stsA(nxt);
            asm volatile("cp.async.wait_group 0;" ::: "memory");
        }
        __syncthreads();
    }

    // ---- row norms: 16-thread groups share a row ----
#pragma unroll
    for (int j = 0; j < 4; j++) {
#pragma unroll
        for (int o = 8; o >= 1; o >>= 1)
            rsq[j] += __shfl_xor_sync(0xffffffffu, rsq[j], o);
    }
    if ((tid & 15) == 0) {
#pragma unroll
        for (int j = 0; j < 4; j++) {
            int row = (tid >> 4) + 32 * j;
            float inv = 1.0f / fmaxf(sqrtf(rsq[j]), 1e-12f);
            sInv[row] = inv;
            g_invn[bm + row] = inv;
        }
    }
    __syncthreads();

    // ---- |acc| * invn -> smem buf ----
    {
        int r0 = warpM + gq;
        float i0 = sInv[r0], i1 = sInv[r0 + 8];
#pragma unroll
        for (int ni = 0; ni < 11; ni++) {
            int c0 = warpN + ni * 8 + 2 * tig;
            buf[r0 * BUFW + c0]       = fabsf(acc[ni][0] * i0);
            buf[r0 * BUFW + c0 + 1]   = fabsf(acc[ni][1] * i0);
            buf[(r0 + 8) * BUFW + c0]     = fabsf(acc[ni][2] * i1);
            buf[(r0 + 8) * BUFW + c0 + 1] = fabsf(acc[ni][3] * i1);
        }
    }
    __syncthreads();

    // ---- fused epilogue: each warp handles 8 rows ----
    for (int rr = 0; rr < 8; rr++) {
        int row = wid * 8 + rr;
        int n = bm + row;
        float mx = -1.f; int bi = NKPT_;
        if (lane < NKPT_) {
            const float* br = buf + row * BUFW + lane * 10;
            mx = br[0];
#pragma unroll
            for (int i = 1; i < 10; i++) mx = fmaxf(mx, br[i]);
            bi = lane;
        }
        float v = mx; int ii = bi;
#pragma unroll
        for (int o = 16; o > 0; o >>= 1) {
            float v2 = __shfl_xor_sync(0xffffffffu, v, o);
            int i2 = __shfl_xor_sync(0xffffffffu, ii, o);
            if (v2 > v || (v2 == v && i2 < ii)) { v = v2; ii = i2; }
        }
        int pred = ii;
        int gcls = gt[n];
        if (lane < NKPT_)
            outKpt[(size_t)n * NKPT_ + lane] = fminf(fmaxf(mx, 1e-4f), 0.9999f);
        if (lane == 0) {
            float ce = (gcls == pred) ? conf[n] : 0.f;
            g_ce[n] = ce;
            atomicAdd(&scnt[gcls], 1.0f);
        }
        if (lane < MC) {
            float e = expf(buf[row * BUFW + gcls * 10 + lane] / EPS_F);
            g_L[lane * NN + n] = e;
            atomicAdd(&scol[gcls * 10 + lane], e);
        }
        __syncwarp();
    }

    // ---- logits store (coalesced within rows) ----
    for (int rr = 0; rr < 8; rr++) {
        int row = wid * 8 + rr;
        for (int c = lane; c < KM; c += 32)
            outSim[(size_t)(bm + row) * KM + c] = buf[row * BUFW + c];
    }

    __syncthreads();
    if (tid < KM) atomicAdd(&g_col[0][tid], scol[tid]);
    if (tid < NKPT_) atomicAdd(&g_cnt[tid], scnt[tid]);
}

// colsum of L(it): recompute chain from stored e, accumulate into g_col[it]
// it = 1: colsum of L1; it = 2: colsum of L2.  (write-free sinkhorn)
__global__ __launch_bounds__(256) void k_colsum(const int* __restrict__ gt, int it) {
    __shared__ float scol[KM];
    int tid = threadIdx.x;
    if (tid < KM) scol[tid] = 0.f;
    __syncthreads();
    int n = blockIdx.x * 256 + tid;
    if (n < NN) {
        int g = gt[n];
        float B = g_cnt[g];
        float t[MC];
        float rs = 0.f;
#pragma unroll
        for (int m = 0; m < MC; m++) {
            t[m] = g_L[m * NN + n] / (g_col[0][g * 10 + m] * 10.0f);
            rs += t[m];
        }
        float den = rs * B;
#pragma unroll
        for (int m = 0; m < MC; m++) t[m] = (rs > 0.f) ? t[m] / den : 0.f;
        if (it == 2) {
            rs = 0.f;
#pragma unroll
            for (int m = 0; m < MC; m++) {
                t[m] = t[m] / (g_col[1][g * 10 + m] * 10.0f);
                rs += t[m];
            }
            den = rs * B;
#pragma unroll
            for (int m = 0; m < MC; m++) t[m] = (rs > 0.f) ? t[m] / den : 0.f;
        }
#pragma unroll
        for (int m = 0; m < MC; m++) atomicAdd(&scol[g * 10 + m], t[m]);
    }
    __syncthreads();
    if (tid < KM) atomicAdd(&g_col[it][tid], scol[tid]);
}

// final: recompute chain, idx argmax, gumbel hard assignment, compact conf list
__global__ __launch_bounds__(256) void k_s3(const int* __restrict__ gt,
                                            float* __restrict__ outTgt) {
    int n = blockIdx.x * 256 + threadIdx.x;
    if (n >= NN) return;
    int g = gt[n];
    float B = g_cnt[g];
    float t[MC];
    float rs = 0.f;
#pragma unroll
    for (int m = 0; m < MC; m++) {
        t[m] = g_L[m * NN + n] / (g_col[0][g * 10 + m] * 10.0f);
        rs += t[m];
    }
    float den = rs * B;
#pragma unroll
    for (int m = 0; m < MC; m++) t[m] = (rs > 0.f) ? t[m] / den : 0.f;
    rs = 0.f;
#pragma unroll
    for (int m = 0; m < MC; m++) {
        t[m] = t[m] / (g_col[1][g * 10 + m] * 10.0f);
        rs += t[m];
    }
    den = rs * B;
#pragma unroll
    for (int m = 0; m < MC; m++) t[m] = (rs > 0.f) ? t[m] / den : 0.f;
    // iteration 3 col step
    rs = 0.f;
#pragma unroll
    for (int m = 0; m < MC; m++) {
        t[m] = t[m] / (g_col[2][g * 10 + m] * 10.0f);
        rs += t[m];
    }
    int idx = 0; float bv = t[0];
#pragma unroll
    for (int m = 1; m < MC; m++) if (t[m] > bv) { bv = t[m]; idx = m; }
    den = rs * B;
    unsigned kk0 = g_keys[g][0], kk1 = g_keys[g][1];
    int h = 0; float bh = -1e30f;
#pragma unroll
    for (int m = 0; m < MC; m++) {
        float a = (rs > 0.f) ? t[m] / den : 0.f;
        float Lf = a * B;
        unsigned j = (unsigned)(n * 10 + m);
        unsigned b0, b1;
        threefry2x32(kk0, kk1, 0u, j, b0, b1);
        unsigned bits = b0 ^ b1;
        float u = __uint_as_float((bits >> 9) | 0x3f800000u) - 1.0f;
        u = fmaxf(u, 1.17549435e-38f);
        float gb = -logf(-logf(u));
        float cand = Lf + gb;
        if (cand > bh) { bh = cand; h = m; }
    }
    outTgt[n] = (float)(idx + 10 * g);
    float ce = g_ce[n];
    if (ce > 0.f) {
        int p = atomicAdd(&g_nconf, 1);
        g_list[p] = n;
        g_hj[n] = h;
        g_w2[n] = ce * ce * g_invn[n];
        atomicAdd(&g_nsum[g * 10 + h], ce);
    }
}

// accumulate f[k,m,:] += ce^2 * featsN[n,:]  (warp per listed row)
__global__ __launch_bounds__(256) void k_faccum(const float* __restrict__ A,
                                                const int* __restrict__ gt) {
    int t = blockIdx.x * 256 + threadIdx.x;
    int w = t >> 5, lane = t & 31;
    int nw = (gridDim.x * 256) >> 5;
    int cnt = g_nconf;
    for (int i = w; i < cnt; i += nw) {
        int n = g_list[i];
        int g = gt[n];
        int h = g_hj[n];
        float w2 = g_w2[n];
        float* frow = &g_f[(size_t)(g * 10 + h) * DD];
        const float4* a = (const float4*)(A + (size_t)n * DD);
#pragma unroll 6
        for (int c = lane; c < DD / 4; c += 32) {
            float4 v = a[c];
            atomicAdd(&frow[4 * c + 0], w2 * v.x);
            atomicAdd(&frow[4 * c + 1], w2 * v.y);
            atomicAdd(&frow[4 * c + 2], w2 * v.z);
            atomicAdd(&frow[4 * c + 3], w2 * v.w);
        }
    }
}

// prototype EMA update + renormalization (block per (k,m))
__global__ __launch_bounds__(256) void k_newproto(float* __restrict__ outNP) {
    __shared__ float red[256];
    __shared__ float buf[DD];
    __shared__ int sup;
    int km = blockIdx.x;
    int k = km / MC;
    int tid = threadIdx.x;
    if (tid == 0) {
        float s = 0.f;
#pragma unroll
        for (int i = 0; i < MC; i++) s += g_nsum[k * MC + i];
        sup = (s > 0.f && g_nsum[km] != 0.f) ? 1 : 0;
    }
    float fs = 0.f;
    for (int d = tid; d < DD; d += 256) { float v = g_f[(size_t)km * DD + d]; fs += v * v; }
    float ftot = blockReduceSum256(fs, red);
    float finv = 1.0f / fmaxf(sqrtf(ftot), 1e-12f);
    int upd = sup;
    float vs = 0.f;
    for (int d = tid; d < DD; d += 256) {
        float pN = g_protoN[(size_t)km * DD + d];
        float fn = g_f[(size_t)km * DD + d] * finv;
        float val = upd ? (0.999f * pN + 0.001f * fn) : pN;
        buf[d] = val;
        vs += val * val;
    }
    float vtot = blockReduceSum256(vs, red);
    float vinv = 1.0f / fmaxf(sqrtf(vtot), 1e-12f);
    for (int d = tid; d < DD; d += 256)
        outNP[(size_t)km * DD + d] = buf[d] * vinv;
}

// ---------------- launch ----------------
extern "C" void kernel_launch(void* const* d_in, const int* in_sizes, int n_in,
                              void* d_out, int out_size) {
    const float* feats = (const float*)d_in[0];
    const int*   gt    = (const int*)d_in[1];
    const float* conf  = (const float*)d_in[2];
    const float* proto = (const float*)d_in[3];

    float* out  = (float*)d_out;
    float* oLog = out;                                 // N*170
    float* oTgt = oLog + (size_t)NN * KM;              // N
    float* oKpt = oTgt + NN;                           // N*17
    float* oNP  = oKpt + (size_t)NN * NKPT_;           // 170*768

    cudaFuncSetAttribute(k_gemm_mma, cudaFuncAttributeMaxDynamicSharedMemorySize, SMEM_GEMM);

    k_init<<<(KM * DD + 255) / 256, 256>>>();
    k_pnorm<<<KM, 256>>>(proto);
    k_gemm_mma<<<NN / 128, 512, SMEM_GEMM>>>(feats, gt, conf, oLog, oKpt);
    k_colsum<<<NN / 256, 256>>>(gt, 1);
    k_colsum<<<NN / 256, 256>>>(gt, 2);
    k_s3<<<NN / 256, 256>>>(gt, oTgt);
    k_faccum<<<512, 256>>>(feats, gt);
    k_newproto<<<KM, 256>>>(oNP);
}